// round 4
// baseline (speedup 1.0000x reference)
#include <cuda_runtime.h>
#include <math.h>

// CSCR fused pipeline for B=32, C=256, H=W=56 on sm_103a.
// Passes: (1) per-pixel channel reduce -> sigmoid(sa)   [reads rgb+ir]
//         (2) per-channel dot(sa,x), ||x||^2            [reads rgb+ir]
//         (3) sim + stable bitonic argsort + pos counts (tiny)
//         (4) srcmap build with extra_fea insertion     (tiny)
//         (5) permuted gather * sa -> out               [reads rgb+ir, writes out]

#define NB  32
#define NC  256
#define NHW 3136
#define NG4 784            // NHW / 4 (float4 groups per plane)
#define EPSF 1e-12f

__device__ __align__(16) float g_sa[NB * NHW];     // sigmoid(sa), [B, HW]
__device__ float g_dot[2][NB * NC];                // dot(sa_sig, x) per (b,c)
__device__ float g_nsq[2][NB * NC];                // ||x||^2 per (b,c)
__device__ int   g_ord[2][NB * NC];                // argsort(sim) ascending
__device__ int   g_srcmap[2][NB * NC];             // out channel -> src channel (-1 = extra_fea)
__device__ int   g_lo[2][NB];                      // lowest-sim channel per (stream,b)
__device__ int   g_n[2];                           // max positive count over batch

__global__ void k_init() { g_n[0] = 0; g_n[1] = 0; }

// ---------------------------------------------------------------------------
// Pass 1: sa = max(mean_c(rgb)+mean_c(ir), max_c(rgb)+max_c(ir)); sigmoid.
// One thread per float4 pixel group; loop over C with deep unroll for MLP.
// ---------------------------------------------------------------------------
__global__ void k_sa(const float* __restrict__ rgb, const float* __restrict__ ir) {
    int g = blockIdx.x * blockDim.x + threadIdx.x;
    int b = blockIdx.y;
    if (g >= NG4) return;

    const float4* r4 = (const float4*)(rgb + (size_t)b * NC * NHW);
    const float4* i4 = (const float4*)(ir  + (size_t)b * NC * NHW);

    float4 sr = make_float4(0.f, 0.f, 0.f, 0.f);
    float4 si = make_float4(0.f, 0.f, 0.f, 0.f);
    float4 mr = make_float4(-3.402823466e38f, -3.402823466e38f, -3.402823466e38f, -3.402823466e38f);
    float4 mi = mr;

    #pragma unroll 8
    for (int c = 0; c < NC; c++) {
        float4 a = r4[c * NG4 + g];
        float4 d = i4[c * NG4 + g];
        sr.x += a.x; sr.y += a.y; sr.z += a.z; sr.w += a.w;
        si.x += d.x; si.y += d.y; si.z += d.z; si.w += d.w;
        mr.x = fmaxf(mr.x, a.x); mr.y = fmaxf(mr.y, a.y);
        mr.z = fmaxf(mr.z, a.z); mr.w = fmaxf(mr.w, a.w);
        mi.x = fmaxf(mi.x, d.x); mi.y = fmaxf(mi.y, d.y);
        mi.z = fmaxf(mi.z, d.z); mi.w = fmaxf(mi.w, d.w);
    }

    const float invC = 1.0f / (float)NC;
    float4 o;
    {
        float sa;
        sa = fmaxf((sr.x + si.x) * invC, mr.x + mi.x); o.x = 1.0f / (1.0f + expf(-sa));
        sa = fmaxf((sr.y + si.y) * invC, mr.y + mi.y); o.y = 1.0f / (1.0f + expf(-sa));
        sa = fmaxf((sr.z + si.z) * invC, mr.z + mi.z); o.z = 1.0f / (1.0f + expf(-sa));
        sa = fmaxf((sr.w + si.w) * invC, mr.w + mi.w); o.w = 1.0f / (1.0f + expf(-sa));
    }
    ((float4*)(g_sa + (size_t)b * NHW))[g] = o;
}

// ---------------------------------------------------------------------------
// Pass 2: per-(b,c,stream) plane reduction: dot(sa_sig, x) and ||x||^2.
// sa plane (12.5 KB/b) stays L2-resident across its 512 reuses.
// ---------------------------------------------------------------------------
__global__ void k_stats(const float* __restrict__ rgb, const float* __restrict__ ir) {
    int c = blockIdx.x, b = blockIdx.y, s = blockIdx.z;
    int tid = threadIdx.x;

    const float* x = (s == 0 ? rgb : ir) + ((size_t)b * NC + c) * NHW;
    const float4* x4  = (const float4*)x;
    const float4* sa4 = (const float4*)(g_sa + (size_t)b * NHW);

    float dot = 0.f, nsq = 0.f;
    for (int g = tid; g < NG4; g += blockDim.x) {
        float4 v = x4[g];
        float4 a = sa4[g];
        dot += v.x * a.x + v.y * a.y + v.z * a.z + v.w * a.w;
        nsq += v.x * v.x + v.y * v.y + v.z * v.z + v.w * v.w;
    }

    __shared__ float sd[256];
    __shared__ float sn[256];
    sd[tid] = dot; sn[tid] = nsq;
    __syncthreads();
    for (int st = 128; st > 0; st >>= 1) {
        if (tid < st) { sd[tid] += sd[tid + st]; sn[tid] += sn[tid + st]; }
        __syncthreads();
    }
    if (tid == 0) {
        g_dot[s][b * NC + c] = sd[0];
        g_nsq[s][b * NC + c] = sn[0];
    }
}

// ---------------------------------------------------------------------------
// Pass 3: per (b, stream): sim = dot/(max(||sa||,eps)*max(||x||,eps)),
// positive count (atomicMax over batch), stable ascending bitonic argsort.
// ---------------------------------------------------------------------------
__global__ void k_sort() {
    int b = blockIdx.x, s = blockIdx.y;
    int tid = threadIdx.x;  // 256 threads == NC

    __shared__ float s_red[256];
    __shared__ int   s_cnt[256];
    __shared__ float s_key[256];
    __shared__ int   s_val[256];
    __shared__ float s_nsa;

    // ||sa_sig||_2 over HW for this batch element
    const float* sa = g_sa + (size_t)b * NHW;
    float acc = 0.f;
    for (int i = tid; i < NHW; i += 256) { float v = sa[i]; acc += v * v; }
    s_red[tid] = acc;
    __syncthreads();
    for (int st = 128; st > 0; st >>= 1) {
        if (tid < st) s_red[tid] += s_red[tid + st];
        __syncthreads();
    }
    if (tid == 0) s_nsa = fmaxf(sqrtf(s_red[0]), EPSF);
    __syncthreads();

    float nx  = fmaxf(sqrtf(g_nsq[s][b * NC + tid]), EPSF);
    float sim = g_dot[s][b * NC + tid] / (s_nsa * nx);

    // positive count -> atomicMax (max over batch, deterministic)
    s_cnt[tid] = (sim > 0.f) ? 1 : 0;
    __syncthreads();
    for (int st = 128; st > 0; st >>= 1) {
        if (tid < st) s_cnt[tid] += s_cnt[tid + st];
        __syncthreads();
    }
    if (tid == 0) atomicMax(&g_n[s], s_cnt[0]);

    // stable ascending bitonic argsort (index tiebreak == jnp.argsort stable)
    s_key[tid] = sim;
    s_val[tid] = tid;
    __syncthreads();
    for (int k = 2; k <= NC; k <<= 1) {
        for (int j = k >> 1; j > 0; j >>= 1) {
            int ixj = tid ^ j;
            if (ixj > tid) {
                float a = s_key[tid], c2 = s_key[ixj];
                int va = s_val[tid], vb = s_val[ixj];
                bool gt = (a > c2) || (a == c2 && va > vb);
                bool lt = (a < c2) || (a == c2 && va < vb);
                bool up = ((tid & k) == 0);
                bool sw = up ? gt : lt;
                if (sw) {
                    s_key[tid] = c2; s_key[ixj] = a;
                    s_val[tid] = vb; s_val[ixj] = va;
                }
            }
            __syncthreads();
        }
    }
    g_ord[s][b * NC + tid] = s_val[tid];
}

// ---------------------------------------------------------------------------
// Pass 4: build source-channel map with extra_fea insertion.
// Stream with the smaller positive count (strict <) gets extra_fea at index
// n_self; channels above shift by one; last sorted channel is dropped.
// ---------------------------------------------------------------------------
__global__ void k_src() {
    int t = threadIdx.x;
    if (t >= 2 * NB) return;
    int s = t >> 5;       // t / 32
    int b = t & 31;

    int n_self  = g_n[s];
    int n_other = g_n[s ^ 1];
    const int* ord = g_ord[s] + b * NC;
    int* src = g_srcmap[s] + b * NC;

    bool ins = (n_other > n_self) && (n_self < NC);
    for (int i = 0; i < NC; i++) {
        int v;
        if (ins) {
            if (i < n_self)       v = ord[i];
            else if (i == n_self) v = -1;          // extra_fea
            else                  v = ord[i - 1];
        } else {
            v = ord[i];
        }
        src[i] = v;
    }
    g_lo[s][b] = ord[0];
}

// ---------------------------------------------------------------------------
// Pass 5: out[s][b,i] = (src>=0 ? x[b,src] : max(rgb[b,lo0], ir[b,lo1])) * sa_sig
// Both streams fused per thread.
// ---------------------------------------------------------------------------
__global__ void k_out(const float* __restrict__ rgb, const float* __restrict__ ir,
                      float* __restrict__ out) {
    int g = blockIdx.x * blockDim.x + threadIdx.x;
    int c = blockIdx.y, b = blockIdx.z;
    if (g >= NG4) return;

    float4 a = ((const float4*)(g_sa + (size_t)b * NHW))[g];

    const float4* rb = (const float4*)(rgb + (size_t)b * NC * NHW);
    const float4* ib = (const float4*)(ir  + (size_t)b * NC * NHW);

    int sr  = g_srcmap[0][b * NC + c];
    int si_ = g_srcmap[1][b * NC + c];
    int lo0 = g_lo[0][b];
    int lo1 = g_lo[1][b];

    float4 vr, vi;
    if (sr >= 0) {
        vr = rb[(size_t)sr * NG4 + g];
    } else {
        float4 p = rb[(size_t)lo0 * NG4 + g];
        float4 q = ib[(size_t)lo1 * NG4 + g];
        vr = make_float4(fmaxf(p.x, q.x), fmaxf(p.y, q.y), fmaxf(p.z, q.z), fmaxf(p.w, q.w));
    }
    if (si_ >= 0) {
        vi = ib[(size_t)si_ * NG4 + g];
    } else {
        float4 p = rb[(size_t)lo0 * NG4 + g];
        float4 q = ib[(size_t)lo1 * NG4 + g];
        vi = make_float4(fmaxf(p.x, q.x), fmaxf(p.y, q.y), fmaxf(p.z, q.z), fmaxf(p.w, q.w));
    }

    float4 orr = make_float4(vr.x * a.x, vr.y * a.y, vr.z * a.z, vr.w * a.w);
    float4 oii = make_float4(vi.x * a.x, vi.y * a.y, vi.z * a.z, vi.w * a.w);

    float4* o_r = (float4*)(out) + ((size_t)b * NC + c) * NG4;
    float4* o_i = (float4*)(out + (size_t)NB * NC * NHW) + ((size_t)b * NC + c) * NG4;
    o_r[g] = orr;
    o_i[g] = oii;
}

extern "C" void kernel_launch(void* const* d_in, const int* in_sizes, int n_in,
                              void* d_out, int out_size) {
    (void)in_sizes; (void)n_in; (void)out_size;
    const float* rgb = (const float*)d_in[0];
    const float* ir  = (const float*)d_in[1];
    float* out = (float*)d_out;

    k_init<<<1, 1>>>();
    k_sa<<<dim3((NG4 + 127) / 128, NB), 128>>>(rgb, ir);
    k_stats<<<dim3(NC, NB, 2), 256>>>(rgb, ir);
    k_sort<<<dim3(NB, 2), 256>>>();
    k_src<<<1, 64>>>();
    k_out<<<dim3((NG4 + 255) / 256, NC, NB), 256>>>(rgb, ir, out);
}

// round 8
// speedup vs baseline: 1.7739x; 1.7739x over previous
#include <cuda_runtime.h>
#include <math.h>

// CSCR fused pipeline, B=32, C=256, H=W=56 (HW=3136), sm_103a.
// k_sa1: partial channel reduce (C split x8)      [reads rgb+ir: 205.5 MB]
// k_sa2: combine partials -> sigmoid(sa)          [reads 9.6 MB partials]
// k_stats: per-(b,c,s) dot(sa,x), ||x||^2         [reads rgb+ir: 205.5 MB]
// k_sort: sim + rank-sort + positive counts       (tiny)
// k_src:  batch-max counts + srcmap build         (tiny)
// k_out:  permuted gather * sa -> out             [reads 205.5, writes 205.5 MB]

#define NB  32
#define NC  256
#define NHW 3136
#define NG4 784            // NHW/4
#define NZ  8              // C-chunks in k_sa1
#define CPZ 32             // channels per chunk
#define EPSF 1e-12f

__device__ __align__(16) float  g_sa[NB * NHW];        // sigmoid(sa)
__device__ __align__(16) float4 g_ps [NZ * NB * NG4];  // partial sum (rgb+ir combined)
__device__ __align__(16) float4 g_pmr[NZ * NB * NG4];  // partial max rgb
__device__ __align__(16) float4 g_pmi[NZ * NB * NG4];  // partial max ir
__device__ float g_dot[2][NB * NC];
__device__ float g_nsq[2][NB * NC];
__device__ int   g_ord[2][NB * NC];
__device__ int   g_srcmap[2][NB * NC];
__device__ int   g_lo[2][NB];
__device__ int   g_cnt[2][NB];

// ---------------------------------------------------------------------------
// Pass 1a: partial per-pixel channel reductions over a 32-channel chunk.
// grid (7, B, 8) x 128 -> 1792 blocks, full-chip parallelism.
// ---------------------------------------------------------------------------
__global__ void __launch_bounds__(128) k_sa1(const float* __restrict__ rgb,
                                             const float* __restrict__ ir) {
    int g = blockIdx.x * blockDim.x + threadIdx.x;
    if (g >= NG4) return;
    int b = blockIdx.y, z = blockIdx.z;

    const float4* r4 = (const float4*)(rgb + (size_t)b * NC * NHW) + (size_t)z * CPZ * NG4;
    const float4* i4 = (const float4*)(ir  + (size_t)b * NC * NHW) + (size_t)z * CPZ * NG4;

    float4 s  = make_float4(0.f, 0.f, 0.f, 0.f);
    float4 mr = make_float4(-3.402823466e38f, -3.402823466e38f, -3.402823466e38f, -3.402823466e38f);
    float4 mi = mr;

    #pragma unroll 8
    for (int c = 0; c < CPZ; c++) {
        float4 a = r4[c * NG4 + g];
        float4 d = i4[c * NG4 + g];
        s.x += a.x + d.x; s.y += a.y + d.y; s.z += a.z + d.z; s.w += a.w + d.w;
        mr.x = fmaxf(mr.x, a.x); mr.y = fmaxf(mr.y, a.y);
        mr.z = fmaxf(mr.z, a.z); mr.w = fmaxf(mr.w, a.w);
        mi.x = fmaxf(mi.x, d.x); mi.y = fmaxf(mi.y, d.y);
        mi.z = fmaxf(mi.z, d.z); mi.w = fmaxf(mi.w, d.w);
    }
    size_t o = ((size_t)z * NB + b) * NG4 + g;
    g_ps[o] = s; g_pmr[o] = mr; g_pmi[o] = mi;
}

// ---------------------------------------------------------------------------
// Pass 1b: combine 8 partials -> sa = max(mean, max_r + max_i) -> sigmoid.
// ---------------------------------------------------------------------------
__global__ void __launch_bounds__(128) k_sa2() {
    int g = blockIdx.x * blockDim.x + threadIdx.x;
    if (g >= NG4) return;
    int b = blockIdx.y;

    float4 s  = make_float4(0.f, 0.f, 0.f, 0.f);
    float4 mr = make_float4(-3.402823466e38f, -3.402823466e38f, -3.402823466e38f, -3.402823466e38f);
    float4 mi = mr;

    #pragma unroll
    for (int z = 0; z < NZ; z++) {
        size_t o = ((size_t)z * NB + b) * NG4 + g;
        float4 ps = g_ps[o], pr = g_pmr[o], pi = g_pmi[o];
        s.x += ps.x; s.y += ps.y; s.z += ps.z; s.w += ps.w;
        mr.x = fmaxf(mr.x, pr.x); mr.y = fmaxf(mr.y, pr.y);
        mr.z = fmaxf(mr.z, pr.z); mr.w = fmaxf(mr.w, pr.w);
        mi.x = fmaxf(mi.x, pi.x); mi.y = fmaxf(mi.y, pi.y);
        mi.z = fmaxf(mi.z, pi.z); mi.w = fmaxf(mi.w, pi.w);
    }
    const float invC = 1.0f / (float)NC;
    float4 o4;
    float sa;
    sa = fmaxf(s.x * invC, mr.x + mi.x); o4.x = 1.0f / (1.0f + expf(-sa));
    sa = fmaxf(s.y * invC, mr.y + mi.y); o4.y = 1.0f / (1.0f + expf(-sa));
    sa = fmaxf(s.z * invC, mr.z + mi.z); o4.z = 1.0f / (1.0f + expf(-sa));
    sa = fmaxf(s.w * invC, mr.w + mi.w); o4.w = 1.0f / (1.0f + expf(-sa));
    ((float4*)(g_sa + (size_t)b * NHW))[g] = o4;
}

// ---------------------------------------------------------------------------
// Pass 2: per-(b,c,s) plane reduction: dot(sa_sig, x), ||x||^2.
// 128 threads, warp-shuffle reduce (1 barrier total). sa plane L2-resident.
// ---------------------------------------------------------------------------
__global__ void __launch_bounds__(128) k_stats(const float* __restrict__ rgb,
                                               const float* __restrict__ ir) {
    int c = blockIdx.x, b = blockIdx.y, s = blockIdx.z;
    int tid = threadIdx.x;

    const float4* x4  = (const float4*)((s == 0 ? rgb : ir) + ((size_t)b * NC + c) * NHW);
    const float4* sa4 = (const float4*)(g_sa + (size_t)b * NHW);

    float dot = 0.f, nsq = 0.f;
    #pragma unroll 4
    for (int g = tid; g < NG4; g += 128) {
        float4 v = x4[g];
        float4 a = sa4[g];
        dot += v.x * a.x + v.y * a.y + v.z * a.z + v.w * a.w;
        nsq += v.x * v.x + v.y * v.y + v.z * v.z + v.w * v.w;
    }
    #pragma unroll
    for (int o = 16; o > 0; o >>= 1) {
        dot += __shfl_down_sync(0xffffffffu, dot, o);
        nsq += __shfl_down_sync(0xffffffffu, nsq, o);
    }
    __shared__ float sd[4], sn[4];
    if ((tid & 31) == 0) { sd[tid >> 5] = dot; sn[tid >> 5] = nsq; }
    __syncthreads();
    if (tid == 0) {
        g_dot[s][b * NC + c] = (sd[0] + sd[1]) + (sd[2] + sd[3]);
        g_nsq[s][b * NC + c] = (sn[0] + sn[1]) + (sn[2] + sn[3]);
    }
}

// ---------------------------------------------------------------------------
// Pass 3: sim -> positive count (syncthreads_count) -> rank-based stable
// ascending argsort (O(C) broadcast shared reads per thread, 2 barriers).
// ---------------------------------------------------------------------------
__global__ void __launch_bounds__(256) k_sort() {
    int b = blockIdx.x, s = blockIdx.y;
    int tid = threadIdx.x;  // 256 == NC

    __shared__ float s_key[NC];
    __shared__ float s_w[8];
    __shared__ float s_nsa;

    // ||sa_sig|| over HW (deterministic tree reduce)
    const float4* sa4 = (const float4*)(g_sa + (size_t)b * NHW);
    float acc = 0.f;
    for (int g = tid; g < NG4; g += 256) {
        float4 v = sa4[g];
        acc += v.x * v.x + v.y * v.y + v.z * v.z + v.w * v.w;
    }
    #pragma unroll
    for (int o = 16; o > 0; o >>= 1) acc += __shfl_down_sync(0xffffffffu, acc, o);
    if ((tid & 31) == 0) s_w[tid >> 5] = acc;
    __syncthreads();
    if (tid == 0) {
        float t = ((s_w[0] + s_w[1]) + (s_w[2] + s_w[3]))
                + ((s_w[4] + s_w[5]) + (s_w[6] + s_w[7]));
        s_nsa = fmaxf(sqrtf(t), EPSF);
    }
    __syncthreads();

    float nx  = fmaxf(sqrtf(g_nsq[s][b * NC + tid]), EPSF);
    float sim = g_dot[s][b * NC + tid] / (s_nsa * nx);
    s_key[tid] = sim;

    int cnt = __syncthreads_count(sim > 0.f);   // barrier also publishes s_key
    if (tid == 0) g_cnt[s][b] = cnt;

    // stable rank: # keys strictly less, plus equal keys with smaller index
    int rank = 0;
    #pragma unroll 8
    for (int j = 0; j < NC; j++) {
        float kj = s_key[j];                     // broadcast, conflict-free
        rank += (kj < sim) || (kj == sim && j < tid);
    }
    g_ord[s][b * NC + rank] = tid;               // channel tid sits at position rank
}

// ---------------------------------------------------------------------------
// Pass 4: batch-max positive counts, then srcmap with extra_fea insertion.
// Stream with the strictly smaller count gets extra_fea at index n_self;
// channels above shift up by one; the last sorted channel is dropped.
// ---------------------------------------------------------------------------
__global__ void k_src() {
    int t = threadIdx.x;
    __shared__ int nmax[2];
    if (t < 2) {
        int m = 0;
        for (int b = 0; b < NB; b++) m = max(m, g_cnt[t][b]);
        nmax[t] = m;
    }
    __syncthreads();
    if (t >= 2 * NB) return;
    int s = t >> 5, b = t & 31;

    int n_self = nmax[s], n_other = nmax[s ^ 1];
    const int* ord = g_ord[s] + b * NC;
    int* src = g_srcmap[s] + b * NC;

    bool ins = (n_other > n_self) && (n_self < NC);
    for (int i = 0; i < NC; i++) {
        int v;
        if (ins) {
            if (i < n_self)       v = ord[i];
            else if (i == n_self) v = -1;        // extra_fea slot
            else                  v = ord[i - 1];
        } else {
            v = ord[i];
        }
        src[i] = v;
    }
    g_lo[s][b] = ord[0];
}

// ---------------------------------------------------------------------------
// Pass 5: out = (src>=0 ? x[src] : max(rgb[lo0], ir[lo1])) * sa_sig.
// Flattened grid: exactly one thread per float4 group, both streams fused.
// ---------------------------------------------------------------------------
__global__ void __launch_bounds__(256) k_out(const float* __restrict__ rgb,
                                             const float* __restrict__ ir,
                                             float* __restrict__ out) {
    int idx = blockIdx.x * blockDim.x + threadIdx.x;     // [0, NB*NC*NG4)
    int g  = idx % NG4;
    int bc = idx / NG4;
    int b  = bc >> 8;

    float4 a = __ldg((const float4*)(g_sa + (size_t)b * NHW) + g);

    const float4* rb = (const float4*)(rgb + (size_t)b * NC * NHW);
    const float4* ib = (const float4*)(ir  + (size_t)b * NC * NHW);

    int sr  = __ldg(&g_srcmap[0][bc]);
    int si_ = __ldg(&g_srcmap[1][bc]);
    int lo0 = __ldg(&g_lo[0][b]);
    int lo1 = __ldg(&g_lo[1][b]);

    float4 vr, vi;
    if (sr >= 0) {
        vr = __ldg(rb + (size_t)sr * NG4 + g);
    } else {
        float4 p = __ldg(rb + (size_t)lo0 * NG4 + g);
        float4 q = __ldg(ib + (size_t)lo1 * NG4 + g);
        vr = make_float4(fmaxf(p.x, q.x), fmaxf(p.y, q.y), fmaxf(p.z, q.z), fmaxf(p.w, q.w));
    }
    if (si_ >= 0) {
        vi = __ldg(ib + (size_t)si_ * NG4 + g);
    } else {
        float4 p = __ldg(rb + (size_t)lo0 * NG4 + g);
        float4 q = __ldg(ib + (size_t)lo1 * NG4 + g);
        vi = make_float4(fmaxf(p.x, q.x), fmaxf(p.y, q.y), fmaxf(p.z, q.z), fmaxf(p.w, q.w));
    }

    float4 orr = make_float4(vr.x * a.x, vr.y * a.y, vr.z * a.z, vr.w * a.w);
    float4 oii = make_float4(vi.x * a.x, vi.y * a.y, vi.z * a.z, vi.w * a.w);

    ((float4*)out)[(size_t)bc * NG4 + g] = orr;
    ((float4*)(out + (size_t)NB * NC * NHW))[(size_t)bc * NG4 + g] = oii;
}

extern "C" void kernel_launch(void* const* d_in, const int* in_sizes, int n_in,
                              void* d_out, int out_size) {
    (void)in_sizes; (void)n_in; (void)out_size;
    const float* rgb = (const float*)d_in[0];
    const float* ir  = (const float*)d_in[1];
    float* out = (float*)d_out;

    k_sa1<<<dim3(7, NB, NZ), 128>>>(rgb, ir);
    k_sa2<<<dim3(7, NB), 128>>>();
    k_stats<<<dim3(NC, NB, 2), 128>>>(rgb, ir);
    k_sort<<<dim3(NB, 2), 256>>>();
    k_src<<<1, 64>>>();
    k_out<<<(NB * NC * NG4) / 256, 256>>>(rgb, ir, out);
}

// round 9
// speedup vs baseline: 2.1987x; 1.2395x over previous
#include <cuda_runtime.h>
#include <math.h>

// CSCR fused pipeline, B=32, C=256, H=W=56 (HW=3136), sm_103a.
// k_sa1: partial channel reduce (C split x8)      [reads rgb+ir: 205.5 MB, streaming]
// k_sa2: combine partials -> sigmoid(sa)          [reads 9.6 MB partials, L2-resident]
// k_stats: per-(b,c,s) dot(sa,x), ||x||^2         [reads rgb+ir: 205.5 MB, streaming]
// k_sort: sim ordering via dot/nx (common positive factor nsa dropped),
//         positive counts, stable rank argsort    (tiny)
// k_nmax: batch-max positive counts               (trivial)
// k_out:  inline srcmap + gather * sa -> out      [reads 205.5, writes 205.5 MB, streaming]

#define NB  32
#define NC  256
#define NHW 3136
#define NG4 784            // NHW/4
#define NZ  8              // C-chunks in k_sa1
#define CPZ 32             // channels per chunk
#define EPSF 1e-12f

__device__ __align__(16) float  g_sa[NB * NHW];        // sigmoid(sa)
__device__ __align__(16) float4 g_ps [NZ * NB * NG4];  // partial sum (rgb+ir combined)
__device__ __align__(16) float4 g_pmr[NZ * NB * NG4];  // partial max rgb
__device__ __align__(16) float4 g_pmi[NZ * NB * NG4];  // partial max ir
__device__ float g_dot[2][NB * NC];
__device__ float g_nsq[2][NB * NC];
__device__ int   g_ord[2][NB * NC];
__device__ int   g_cnt[2][NB];
__device__ int   g_n[2];

// ---------------------------------------------------------------------------
// Pass 1a: partial per-pixel channel reductions over a 32-channel chunk.
// grid (7, B, 8) x 128 -> 1792 blocks. Streaming loads (touch-once).
// ---------------------------------------------------------------------------
__global__ void __launch_bounds__(128) k_sa1(const float* __restrict__ rgb,
                                             const float* __restrict__ ir) {
    int g = blockIdx.x * blockDim.x + threadIdx.x;
    if (g >= NG4) return;
    int b = blockIdx.y, z = blockIdx.z;

    const float4* r4 = (const float4*)(rgb + (size_t)b * NC * NHW) + (size_t)z * CPZ * NG4;
    const float4* i4 = (const float4*)(ir  + (size_t)b * NC * NHW) + (size_t)z * CPZ * NG4;

    float4 s  = make_float4(0.f, 0.f, 0.f, 0.f);
    float4 mr = make_float4(-3.402823466e38f, -3.402823466e38f, -3.402823466e38f, -3.402823466e38f);
    float4 mi = mr;

    #pragma unroll 8
    for (int c = 0; c < CPZ; c++) {
        float4 a = __ldcs(r4 + c * NG4 + g);
        float4 d = __ldcs(i4 + c * NG4 + g);
        s.x += a.x + d.x; s.y += a.y + d.y; s.z += a.z + d.z; s.w += a.w + d.w;
        mr.x = fmaxf(mr.x, a.x); mr.y = fmaxf(mr.y, a.y);
        mr.z = fmaxf(mr.z, a.z); mr.w = fmaxf(mr.w, a.w);
        mi.x = fmaxf(mi.x, d.x); mi.y = fmaxf(mi.y, d.y);
        mi.z = fmaxf(mi.z, d.z); mi.w = fmaxf(mi.w, d.w);
    }
    size_t o = ((size_t)z * NB + b) * NG4 + g;
    g_ps[o] = s; g_pmr[o] = mr; g_pmi[o] = mi;   // default policy: want L2 residency
}

// ---------------------------------------------------------------------------
// Pass 1b: combine 8 partials -> sa = max(mean, max_r + max_i) -> sigmoid.
// Partials are L2-resident (9.6 MB).
// ---------------------------------------------------------------------------
__global__ void __launch_bounds__(128) k_sa2() {
    int g = blockIdx.x * blockDim.x + threadIdx.x;
    if (g >= NG4) return;
    int b = blockIdx.y;

    float4 s  = make_float4(0.f, 0.f, 0.f, 0.f);
    float4 mr = make_float4(-3.402823466e38f, -3.402823466e38f, -3.402823466e38f, -3.402823466e38f);
    float4 mi = mr;

    #pragma unroll
    for (int z = 0; z < NZ; z++) {
        size_t o = ((size_t)z * NB + b) * NG4 + g;
        float4 ps = g_ps[o], pr = g_pmr[o], pi = g_pmi[o];
        s.x += ps.x; s.y += ps.y; s.z += ps.z; s.w += ps.w;
        mr.x = fmaxf(mr.x, pr.x); mr.y = fmaxf(mr.y, pr.y);
        mr.z = fmaxf(mr.z, pr.z); mr.w = fmaxf(mr.w, pr.w);
        mi.x = fmaxf(mi.x, pi.x); mi.y = fmaxf(mi.y, pi.y);
        mi.z = fmaxf(mi.z, pi.z); mi.w = fmaxf(mi.w, pi.w);
    }
    const float invC = 1.0f / (float)NC;
    float4 o4;
    float sa;
    sa = fmaxf(s.x * invC, mr.x + mi.x); o4.x = 1.0f / (1.0f + expf(-sa));
    sa = fmaxf(s.y * invC, mr.y + mi.y); o4.y = 1.0f / (1.0f + expf(-sa));
    sa = fmaxf(s.z * invC, mr.z + mi.z); o4.z = 1.0f / (1.0f + expf(-sa));
    sa = fmaxf(s.w * invC, mr.w + mi.w); o4.w = 1.0f / (1.0f + expf(-sa));
    ((float4*)(g_sa + (size_t)b * NHW))[g] = o4;
}

// ---------------------------------------------------------------------------
// Pass 2: per-(b,c,s) plane reduction: dot(sa_sig, x), ||x||^2.
// x streamed (touch-once); sa plane stays L2-resident for its 512 reuses.
// ---------------------------------------------------------------------------
__global__ void __launch_bounds__(128) k_stats(const float* __restrict__ rgb,
                                               const float* __restrict__ ir) {
    int c = blockIdx.x, b = blockIdx.y, s = blockIdx.z;
    int tid = threadIdx.x;

    const float4* x4  = (const float4*)((s == 0 ? rgb : ir) + ((size_t)b * NC + c) * NHW);
    const float4* sa4 = (const float4*)(g_sa + (size_t)b * NHW);

    float dot = 0.f, nsq = 0.f;
    #pragma unroll 4
    for (int g = tid; g < NG4; g += 128) {
        float4 v = __ldcs(x4 + g);
        float4 a = sa4[g];
        dot += v.x * a.x + v.y * a.y + v.z * a.z + v.w * a.w;
        nsq += v.x * v.x + v.y * v.y + v.z * v.z + v.w * v.w;
    }
    #pragma unroll
    for (int o = 16; o > 0; o >>= 1) {
        dot += __shfl_down_sync(0xffffffffu, dot, o);
        nsq += __shfl_down_sync(0xffffffffu, nsq, o);
    }
    __shared__ float sd[4], sn[4];
    if ((tid & 31) == 0) { sd[tid >> 5] = dot; sn[tid >> 5] = nsq; }
    __syncthreads();
    if (tid == 0) {
        g_dot[s][b * NC + c] = (sd[0] + sd[1]) + (sd[2] + sd[3]);
        g_nsq[s][b * NC + c] = (sn[0] + sn[1]) + (sn[2] + sn[3]);
    }
}

// ---------------------------------------------------------------------------
// Pass 3: ordering key = dot / nx. The reference key is dot/(nsa*nx) with
// nsa = max(||sa||,eps) > 0 a COMMON factor per (b): identical argsort order
// and identical sign, so nsa is dropped entirely (no global sa reduction).
// Positive count via __syncthreads_count; stable rank argsort (2 barriers).
// ---------------------------------------------------------------------------
__global__ void __launch_bounds__(256) k_sort() {
    int b = blockIdx.x, s = blockIdx.y;
    int tid = threadIdx.x;  // 256 == NC

    __shared__ float s_key[NC];

    float nx  = fmaxf(sqrtf(g_nsq[s][b * NC + tid]), EPSF);
    float sim = g_dot[s][b * NC + tid] / nx;
    s_key[tid] = sim;

    int cnt = __syncthreads_count(sim > 0.f);   // barrier also publishes s_key
    if (tid == 0) g_cnt[s][b] = cnt;

    // stable rank: # keys strictly less, plus equal keys with smaller index
    int rank = 0;
    #pragma unroll 8
    for (int j = 0; j < NC; j++) {
        float kj = s_key[j];                     // broadcast, conflict-free
        rank += (kj < sim) || (kj == sim && j < tid);
    }
    g_ord[s][b * NC + rank] = tid;               // channel tid sits at position rank
}

// ---------------------------------------------------------------------------
// Pass 4: batch-max positive count per stream (two warp maxes).
// ---------------------------------------------------------------------------
__global__ void k_nmax() {
    int t = threadIdx.x;          // 64 threads: warp 0 -> stream 0, warp 1 -> stream 1
    int s = t >> 5;
    int v = g_cnt[s][t & 31];
    #pragma unroll
    for (int o = 16; o > 0; o >>= 1) v = max(v, __shfl_down_sync(0xffffffffu, v, o));
    if ((t & 31) == 0) g_n[s] = v;
}

// ---------------------------------------------------------------------------
// Pass 5: out = (src>=0 ? x[src] : max(rgb[lo0], ir[lo1])) * sa_sig.
// Source channel derived inline: the stream with strictly smaller positive
// count gets extra_fea inserted at index n_self (channels above shift by one,
// last sorted channel dropped). Streaming loads/stores for touch-once data.
// ---------------------------------------------------------------------------
__device__ __forceinline__ int src_of(const int* __restrict__ ord, int c,
                                      int n_self, int n_other) {
    if (n_other > n_self && n_self < NC) {
        if (c < n_self)  return __ldg(ord + c);
        if (c == n_self) return -1;              // extra_fea slot
        return __ldg(ord + c - 1);
    }
    return __ldg(ord + c);
}

__global__ void __launch_bounds__(256) k_out(const float* __restrict__ rgb,
                                             const float* __restrict__ ir,
                                             float* __restrict__ out) {
    int idx = blockIdx.x * blockDim.x + threadIdx.x;     // [0, NB*NC*NG4)
    int g  = idx % NG4;
    int bc = idx / NG4;
    int c  = bc & (NC - 1);
    int b  = bc >> 8;

    float4 a = __ldg((const float4*)(g_sa + (size_t)b * NHW) + g);

    const float4* rb = (const float4*)(rgb + (size_t)b * NC * NHW);
    const float4* ib = (const float4*)(ir  + (size_t)b * NC * NHW);

    int n0 = __ldg(&g_n[0]);
    int n1 = __ldg(&g_n[1]);
    const int* ord0 = g_ord[0] + b * NC;
    const int* ord1 = g_ord[1] + b * NC;

    int sr  = src_of(ord0, c, n0, n1);
    int si_ = src_of(ord1, c, n1, n0);

    float4 vr, vi;
    if (sr >= 0) {
        vr = __ldcs(rb + (size_t)sr * NG4 + g);
    } else {
        float4 p = __ldcs(rb + (size_t)__ldg(ord0) * NG4 + g);
        float4 q = __ldcs(ib + (size_t)__ldg(ord1) * NG4 + g);
        vr = make_float4(fmaxf(p.x, q.x), fmaxf(p.y, q.y), fmaxf(p.z, q.z), fmaxf(p.w, q.w));
    }
    if (si_ >= 0) {
        vi = __ldcs(ib + (size_t)si_ * NG4 + g);
    } else {
        float4 p = __ldcs(rb + (size_t)__ldg(ord0) * NG4 + g);
        float4 q = __ldcs(ib + (size_t)__ldg(ord1) * NG4 + g);
        vi = make_float4(fmaxf(p.x, q.x), fmaxf(p.y, q.y), fmaxf(p.z, q.z), fmaxf(p.w, q.w));
    }

    float4 orr = make_float4(vr.x * a.x, vr.y * a.y, vr.z * a.z, vr.w * a.w);
    float4 oii = make_float4(vi.x * a.x, vi.y * a.y, vi.z * a.z, vi.w * a.w);

    __stcs((float4*)out + (size_t)bc * NG4 + g, orr);
    __stcs((float4*)(out + (size_t)NB * NC * NHW) + (size_t)bc * NG4 + g, oii);
}

extern "C" void kernel_launch(void* const* d_in, const int* in_sizes, int n_in,
                              void* d_out, int out_size) {
    (void)in_sizes; (void)n_in; (void)out_size;
    const float* rgb = (const float*)d_in[0];
    const float* ir  = (const float*)d_in[1];
    float* out = (float*)d_out;

    k_sa1<<<dim3(7, NB, NZ), 128>>>(rgb, ir);
    k_sa2<<<dim3(7, NB), 128>>>();
    k_stats<<<dim3(NC, NB, 2), 128>>>(rgb, ir);
    k_sort<<<dim3(NB, 2), 256>>>();
    k_nmax<<<1, 64>>>();
    k_out<<<(NB * NC * NG4) / 256, 256>>>(rgb, ir, out);
}

// round 10
// speedup vs baseline: 2.3379x; 1.0633x over previous
#include <cuda_runtime.h>
#include <math.h>

// CSCR fused pipeline, B=32, C=256, H=W=56 (HW=3136), sm_103a.
// k_sa1: partial channel reduce (C split x8)      [reads rgb+ir: 205.5 MB, streaming]
// k_sa2: combine partials -> sigmoid(sa)          [reads 9.6 MB partials, L2-resident]
// k_stats: 4-ch blocks: dot(sa,x), ||x||^2        [reads rgb+ir: 205.5 MB, streaming; sa shared 4x]
// k_sort: key = dot/nx (common factor nsa dropped), positive counts,
//         stable rank argsort with LDS.128 loop   (tiny)
// k_nmax: batch-max positive counts               (trivial)
// k_out:  2-ch/thread inline srcmap gather * sa   [reads 205.5, writes 205.5 MB, streaming]

#define NB  32
#define NC  256
#define NHW 3136
#define NG4 784            // NHW/4
#define NZ  8              // C-chunks in k_sa1
#define CPZ 32             // channels per chunk
#define EPSF 1e-12f

__device__ __align__(16) float  g_sa[NB * NHW];        // sigmoid(sa)
__device__ __align__(16) float4 g_ps [NZ * NB * NG4];  // partial sum (rgb+ir combined)
__device__ __align__(16) float4 g_pmr[NZ * NB * NG4];  // partial max rgb
__device__ __align__(16) float4 g_pmi[NZ * NB * NG4];  // partial max ir
__device__ float g_dot[2][NB * NC];
__device__ float g_nsq[2][NB * NC];
__device__ int   g_ord[2][NB * NC];
__device__ int   g_cnt[2][NB];
__device__ int   g_n[2];

// ---------------------------------------------------------------------------
// Pass 1a: partial per-pixel channel reductions over a 32-channel chunk.
// grid (7, B, 8) x 128 -> 1792 blocks. Streaming loads (touch-once).
// ---------------------------------------------------------------------------
__global__ void __launch_bounds__(128) k_sa1(const float* __restrict__ rgb,
                                             const float* __restrict__ ir) {
    int g = blockIdx.x * blockDim.x + threadIdx.x;
    if (g >= NG4) return;
    int b = blockIdx.y, z = blockIdx.z;

    const float4* r4 = (const float4*)(rgb + (size_t)b * NC * NHW) + (size_t)z * CPZ * NG4;
    const float4* i4 = (const float4*)(ir  + (size_t)b * NC * NHW) + (size_t)z * CPZ * NG4;

    float4 s  = make_float4(0.f, 0.f, 0.f, 0.f);
    float4 mr = make_float4(-3.402823466e38f, -3.402823466e38f, -3.402823466e38f, -3.402823466e38f);
    float4 mi = mr;

    #pragma unroll 8
    for (int c = 0; c < CPZ; c++) {
        float4 a = __ldcs(r4 + c * NG4 + g);
        float4 d = __ldcs(i4 + c * NG4 + g);
        s.x += a.x + d.x; s.y += a.y + d.y; s.z += a.z + d.z; s.w += a.w + d.w;
        mr.x = fmaxf(mr.x, a.x); mr.y = fmaxf(mr.y, a.y);
        mr.z = fmaxf(mr.z, a.z); mr.w = fmaxf(mr.w, a.w);
        mi.x = fmaxf(mi.x, d.x); mi.y = fmaxf(mi.y, d.y);
        mi.z = fmaxf(mi.z, d.z); mi.w = fmaxf(mi.w, d.w);
    }
    size_t o = ((size_t)z * NB + b) * NG4 + g;
    g_ps[o] = s; g_pmr[o] = mr; g_pmi[o] = mi;   // default policy: L2-resident
}

// ---------------------------------------------------------------------------
// Pass 1b: combine 8 partials -> sa = max(mean, max_r + max_i) -> sigmoid.
// ---------------------------------------------------------------------------
__global__ void __launch_bounds__(128) k_sa2() {
    int g = blockIdx.x * blockDim.x + threadIdx.x;
    if (g >= NG4) return;
    int b = blockIdx.y;

    float4 s  = make_float4(0.f, 0.f, 0.f, 0.f);
    float4 mr = make_float4(-3.402823466e38f, -3.402823466e38f, -3.402823466e38f, -3.402823466e38f);
    float4 mi = mr;

    #pragma unroll
    for (int z = 0; z < NZ; z++) {
        size_t o = ((size_t)z * NB + b) * NG4 + g;
        float4 ps = g_ps[o], pr = g_pmr[o], pi = g_pmi[o];
        s.x += ps.x; s.y += ps.y; s.z += ps.z; s.w += ps.w;
        mr.x = fmaxf(mr.x, pr.x); mr.y = fmaxf(mr.y, pr.y);
        mr.z = fmaxf(mr.z, pr.z); mr.w = fmaxf(mr.w, pr.w);
        mi.x = fmaxf(mi.x, pi.x); mi.y = fmaxf(mi.y, pi.y);
        mi.z = fmaxf(mi.z, pi.z); mi.w = fmaxf(mi.w, pi.w);
    }
    const float invC = 1.0f / (float)NC;
    float4 o4;
    float sa;
    sa = fmaxf(s.x * invC, mr.x + mi.x); o4.x = 1.0f / (1.0f + expf(-sa));
    sa = fmaxf(s.y * invC, mr.y + mi.y); o4.y = 1.0f / (1.0f + expf(-sa));
    sa = fmaxf(s.z * invC, mr.z + mi.z); o4.z = 1.0f / (1.0f + expf(-sa));
    sa = fmaxf(s.w * invC, mr.w + mi.w); o4.w = 1.0f / (1.0f + expf(-sa));
    ((float4*)(g_sa + (size_t)b * NHW))[g] = o4;
}

// ---------------------------------------------------------------------------
// Pass 2: 4 channels per block — one sa load feeds 4 dot accumulations,
// cutting sa L2 traffic 4x. x streamed (touch-once).
// ---------------------------------------------------------------------------
__global__ void __launch_bounds__(128) k_stats(const float* __restrict__ rgb,
                                               const float* __restrict__ ir) {
    int c0 = blockIdx.x * 4, b = blockIdx.y, s = blockIdx.z;
    int tid = threadIdx.x;

    const float4* x4  = (const float4*)((s == 0 ? rgb : ir) + ((size_t)b * NC + c0) * NHW);
    const float4* sa4 = (const float4*)(g_sa + (size_t)b * NHW);

    float d0 = 0.f, d1 = 0.f, d2 = 0.f, d3 = 0.f;
    float n0 = 0.f, n1 = 0.f, n2 = 0.f, n3 = 0.f;
    #pragma unroll 2
    for (int g = tid; g < NG4; g += 128) {
        float4 a  = sa4[g];
        float4 v0 = __ldcs(x4 + 0 * NG4 + g);
        float4 v1 = __ldcs(x4 + 1 * NG4 + g);
        float4 v2 = __ldcs(x4 + 2 * NG4 + g);
        float4 v3 = __ldcs(x4 + 3 * NG4 + g);
        d0 += v0.x * a.x + v0.y * a.y + v0.z * a.z + v0.w * a.w;
        n0 += v0.x * v0.x + v0.y * v0.y + v0.z * v0.z + v0.w * v0.w;
        d1 += v1.x * a.x + v1.y * a.y + v1.z * a.z + v1.w * a.w;
        n1 += v1.x * v1.x + v1.y * v1.y + v1.z * v1.z + v1.w * v1.w;
        d2 += v2.x * a.x + v2.y * a.y + v2.z * a.z + v2.w * a.w;
        n2 += v2.x * v2.x + v2.y * v2.y + v2.z * v2.z + v2.w * v2.w;
        d3 += v3.x * a.x + v3.y * a.y + v3.z * a.z + v3.w * a.w;
        n3 += v3.x * v3.x + v3.y * v3.y + v3.z * v3.z + v3.w * v3.w;
    }
    #pragma unroll
    for (int o = 16; o > 0; o >>= 1) {
        d0 += __shfl_down_sync(0xffffffffu, d0, o);
        n0 += __shfl_down_sync(0xffffffffu, n0, o);
        d1 += __shfl_down_sync(0xffffffffu, d1, o);
        n1 += __shfl_down_sync(0xffffffffu, n1, o);
        d2 += __shfl_down_sync(0xffffffffu, d2, o);
        n2 += __shfl_down_sync(0xffffffffu, n2, o);
        d3 += __shfl_down_sync(0xffffffffu, d3, o);
        n3 += __shfl_down_sync(0xffffffffu, n3, o);
    }
    __shared__ float sd[4][4], sn[4][4];   // [warp][channel]
    if ((tid & 31) == 0) {
        int w = tid >> 5;
        sd[w][0] = d0; sd[w][1] = d1; sd[w][2] = d2; sd[w][3] = d3;
        sn[w][0] = n0; sn[w][1] = n1; sn[w][2] = n2; sn[w][3] = n3;
    }
    __syncthreads();
    if (tid < 4) {
        float dd = (sd[0][tid] + sd[1][tid]) + (sd[2][tid] + sd[3][tid]);
        float nn = (sn[0][tid] + sn[1][tid]) + (sn[2][tid] + sn[3][tid]);
        g_dot[s][b * NC + c0 + tid] = dd;
        g_nsq[s][b * NC + c0 + tid] = nn;
    }
}

// ---------------------------------------------------------------------------
// Pass 3: ordering key = dot / nx (common positive factor ||sa|| dropped:
// identical argsort order and sign). Positive count via __syncthreads_count;
// stable rank argsort with vectorized LDS.128 broadcast loop.
// ---------------------------------------------------------------------------
__global__ void __launch_bounds__(256) k_sort() {
    int b = blockIdx.x, s = blockIdx.y;
    int tid = threadIdx.x;  // 256 == NC

    __shared__ __align__(16) float s_key[NC];

    float nx  = fmaxf(sqrtf(g_nsq[s][b * NC + tid]), EPSF);
    float sim = g_dot[s][b * NC + tid] / nx;
    s_key[tid] = sim;

    int cnt = __syncthreads_count(sim > 0.f);   // barrier also publishes s_key
    if (tid == 0) g_cnt[s][b] = cnt;

    // stable rank: # keys strictly less, plus equal keys with smaller index
    const float4* k4 = (const float4*)s_key;
    int rank = 0;
    #pragma unroll 8
    for (int j4 = 0; j4 < NC / 4; j4++) {
        float4 k = k4[j4];                       // broadcast LDS.128
        int j = j4 * 4;
        rank += (k.x < sim) || (k.x == sim && j     < tid);
        rank += (k.y < sim) || (k.y == sim && j + 1 < tid);
        rank += (k.z < sim) || (k.z == sim && j + 2 < tid);
        rank += (k.w < sim) || (k.w == sim && j + 3 < tid);
    }
    g_ord[s][b * NC + rank] = tid;               // channel tid sits at position rank
}

// ---------------------------------------------------------------------------
// Pass 4: batch-max positive count per stream (two warp maxes).
// ---------------------------------------------------------------------------
__global__ void k_nmax() {
    int t = threadIdx.x;          // 64 threads: warp 0 -> stream 0, warp 1 -> stream 1
    int s = t >> 5;
    int v = g_cnt[s][t & 31];
    #pragma unroll
    for (int o = 16; o > 0; o >>= 1) v = max(v, __shfl_down_sync(0xffffffffu, v, o));
    if ((t & 31) == 0) g_n[s] = v;
}

// ---------------------------------------------------------------------------
// Pass 5: out = (src>=0 ? x[src] : max(rgb[lo0], ir[lo1])) * sa_sig.
// 2 channels per thread (same b,g): one sa load + one metadata set feeds
// 4 gathers/4 stores; srcmap derived inline from g_ord + g_n.
// ---------------------------------------------------------------------------
__device__ __forceinline__ int src_of(const int* __restrict__ ord, int c,
                                      int n_self, int n_other) {
    if (n_other > n_self && n_self < NC) {
        if (c < n_self)  return __ldg(ord + c);
        if (c == n_self) return -1;              // extra_fea slot
        return __ldg(ord + c - 1);
    }
    return __ldg(ord + c);
}

__global__ void __launch_bounds__(256) k_out(const float* __restrict__ rgb,
                                             const float* __restrict__ ir,
                                             float* __restrict__ out) {
    int idx = blockIdx.x * blockDim.x + threadIdx.x;     // [0, NB*128*NG4)
    int g  = idx % NG4;
    int t  = idx / NG4;
    int cp = t & 127;
    int b  = t >> 7;
    int c0 = cp * 2, c1 = c0 + 1;

    float4 a = __ldg((const float4*)(g_sa + (size_t)b * NHW) + g);

    const float4* rb = (const float4*)(rgb + (size_t)b * NC * NHW);
    const float4* ib = (const float4*)(ir  + (size_t)b * NC * NHW);

    int n0 = __ldg(&g_n[0]);
    int n1 = __ldg(&g_n[1]);
    const int* ord0 = g_ord[0] + b * NC;
    const int* ord1 = g_ord[1] + b * NC;

    int sr0 = src_of(ord0, c0, n0, n1);
    int sr1 = src_of(ord0, c1, n0, n1);
    int si0 = src_of(ord1, c0, n1, n0);
    int si1 = src_of(ord1, c1, n1, n0);

    float4 ex;  // extra_fea = max(lowest-sim rgb, lowest-sim ir); computed lazily
    bool need_ex = (sr0 < 0) | (sr1 < 0) | (si0 < 0) | (si1 < 0);
    if (need_ex) {
        float4 p = __ldcs(rb + (size_t)__ldg(ord0) * NG4 + g);
        float4 q = __ldcs(ib + (size_t)__ldg(ord1) * NG4 + g);
        ex = make_float4(fmaxf(p.x, q.x), fmaxf(p.y, q.y), fmaxf(p.z, q.z), fmaxf(p.w, q.w));
    }

    float4 vr0 = (sr0 >= 0) ? __ldcs(rb + (size_t)sr0 * NG4 + g) : ex;
    float4 vr1 = (sr1 >= 0) ? __ldcs(rb + (size_t)sr1 * NG4 + g) : ex;
    float4 vi0 = (si0 >= 0) ? __ldcs(ib + (size_t)si0 * NG4 + g) : ex;
    float4 vi1 = (si1 >= 0) ? __ldcs(ib + (size_t)si1 * NG4 + g) : ex;

    size_t base_r = ((size_t)b * NC + c0) * NG4 + g;
    size_t base_i = (size_t)NB * NC * NG4 + base_r;

    __stcs((float4*)out + base_r,
           make_float4(vr0.x * a.x, vr0.y * a.y, vr0.z * a.z, vr0.w * a.w));
    __stcs((float4*)out + base_r + NG4,
           make_float4(vr1.x * a.x, vr1.y * a.y, vr1.z * a.z, vr1.w * a.w));
    __stcs((float4*)out + base_i,
           make_float4(vi0.x * a.x, vi0.y * a.y, vi0.z * a.z, vi0.w * a.w));
    __stcs((float4*)out + base_i + NG4,
           make_float4(vi1.x * a.x, vi1.y * a.y, vi1.z * a.z, vi1.w * a.w));
}

extern "C" void kernel_launch(void* const* d_in, const int* in_sizes, int n_in,
                              void* d_out, int out_size) {
    (void)in_sizes; (void)n_in; (void)out_size;
    const float* rgb = (const float*)d_in[0];
    const float* ir  = (const float*)d_in[1];
    float* out = (float*)d_out;

    k_sa1<<<dim3(7, NB, NZ), 128>>>(rgb, ir);
    k_sa2<<<dim3(7, NB), 128>>>();
    k_stats<<<dim3(NC / 4, NB, 2), 128>>>(rgb, ir);
    k_sort<<<dim3(NB, 2), 256>>>();
    k_nmax<<<1, 64>>>();
    k_out<<<(NB * 128 * NG4) / 256, 256>>>(rgb, ir, out);
}

// round 11
// speedup vs baseline: 2.3532x; 1.0065x over previous
#include <cuda_runtime.h>
#include <math.h>

// CSCR fused pipeline, B=32, C=256, H=W=56 (HW=3136), sm_103a.
// k_sa1: partial channel reduce (C split x8) + g_n reset  [reads 205.5 MB, streaming]
// k_sa2: combine partials -> sigmoid(sa)                   [reads 9.6 MB, L2-resident]
// k_stats: 8-ch blocks: dot(sa,x), ||x||^2                 [reads 205.5 MB, streaming]
// k_sort: key = dot/nx, positive counts -> atomicMax(g_n), stable rank argsort
// k_out: 4-ch/thread inline srcmap gather * sa             [reads 205.5, writes 205.5 MB]

#define NB  32
#define NC  256
#define NHW 3136
#define NG4 784            // NHW/4
#define NZ  8              // C-chunks in k_sa1
#define CPZ 32             // channels per chunk
#define EPSF 1e-12f

__device__ __align__(16) float  g_sa[NB * NHW];        // sigmoid(sa)
__device__ __align__(16) float4 g_ps [NZ * NB * NG4];  // partial sum (rgb+ir combined)
__device__ __align__(16) float4 g_pmr[NZ * NB * NG4];  // partial max rgb
__device__ __align__(16) float4 g_pmi[NZ * NB * NG4];  // partial max ir
__device__ float g_dot[2][NB * NC];
__device__ float g_nsq[2][NB * NC];
__device__ int   g_ord[2][NB * NC];
__device__ int   g_n[2];

// ---------------------------------------------------------------------------
// Pass 1a: partial per-pixel channel reductions over a 32-channel chunk.
// grid (7, B, 8) x 128. Streaming loads. Block (0,0,0) also resets g_n
// (read only by k_sort's atomicMax / k_out, both in later kernels).
// ---------------------------------------------------------------------------
__global__ void __launch_bounds__(128) k_sa1(const float* __restrict__ rgb,
                                             const float* __restrict__ ir) {
    if (blockIdx.x == 0 && blockIdx.y == 0 && blockIdx.z == 0 && threadIdx.x < 2)
        g_n[threadIdx.x] = 0;

    int g = blockIdx.x * blockDim.x + threadIdx.x;
    if (g >= NG4) return;
    int b = blockIdx.y, z = blockIdx.z;

    const float4* r4 = (const float4*)(rgb + (size_t)b * NC * NHW) + (size_t)z * CPZ * NG4;
    const float4* i4 = (const float4*)(ir  + (size_t)b * NC * NHW) + (size_t)z * CPZ * NG4;

    float4 s  = make_float4(0.f, 0.f, 0.f, 0.f);
    float4 mr = make_float4(-3.402823466e38f, -3.402823466e38f, -3.402823466e38f, -3.402823466e38f);
    float4 mi = mr;

    #pragma unroll 8
    for (int c = 0; c < CPZ; c++) {
        float4 a = __ldcs(r4 + c * NG4 + g);
        float4 d = __ldcs(i4 + c * NG4 + g);
        s.x += a.x + d.x; s.y += a.y + d.y; s.z += a.z + d.z; s.w += a.w + d.w;
        mr.x = fmaxf(mr.x, a.x); mr.y = fmaxf(mr.y, a.y);
        mr.z = fmaxf(mr.z, a.z); mr.w = fmaxf(mr.w, a.w);
        mi.x = fmaxf(mi.x, d.x); mi.y = fmaxf(mi.y, d.y);
        mi.z = fmaxf(mi.z, d.z); mi.w = fmaxf(mi.w, d.w);
    }
    size_t o = ((size_t)z * NB + b) * NG4 + g;
    g_ps[o] = s; g_pmr[o] = mr; g_pmi[o] = mi;   // default policy: L2-resident
}

// ---------------------------------------------------------------------------
// Pass 1b: combine 8 partials -> sa = max(mean, max_r + max_i) -> sigmoid.
// ---------------------------------------------------------------------------
__global__ void __launch_bounds__(128) k_sa2() {
    int g = blockIdx.x * blockDim.x + threadIdx.x;
    if (g >= NG4) return;
    int b = blockIdx.y;

    float4 s  = make_float4(0.f, 0.f, 0.f, 0.f);
    float4 mr = make_float4(-3.402823466e38f, -3.402823466e38f, -3.402823466e38f, -3.402823466e38f);
    float4 mi = mr;

    #pragma unroll
    for (int z = 0; z < NZ; z++) {
        size_t o = ((size_t)z * NB + b) * NG4 + g;
        float4 ps = g_ps[o], pr = g_pmr[o], pi = g_pmi[o];
        s.x += ps.x; s.y += ps.y; s.z += ps.z; s.w += ps.w;
        mr.x = fmaxf(mr.x, pr.x); mr.y = fmaxf(mr.y, pr.y);
        mr.z = fmaxf(mr.z, pr.z); mr.w = fmaxf(mr.w, pr.w);
        mi.x = fmaxf(mi.x, pi.x); mi.y = fmaxf(mi.y, pi.y);
        mi.z = fmaxf(mi.z, pi.z); mi.w = fmaxf(mi.w, pi.w);
    }
    const float invC = 1.0f / (float)NC;
    float4 o4;
    float sa;
    sa = fmaxf(s.x * invC, mr.x + mi.x); o4.x = 1.0f / (1.0f + expf(-sa));
    sa = fmaxf(s.y * invC, mr.y + mi.y); o4.y = 1.0f / (1.0f + expf(-sa));
    sa = fmaxf(s.z * invC, mr.z + mi.z); o4.z = 1.0f / (1.0f + expf(-sa));
    sa = fmaxf(s.w * invC, mr.w + mi.w); o4.w = 1.0f / (1.0f + expf(-sa));
    ((float4*)(g_sa + (size_t)b * NHW))[g] = o4;
}

// ---------------------------------------------------------------------------
// Pass 2: 8 channels per block — one sa load feeds 8 dot accumulations
// (sa L2 traffic /8); 8 independent streaming loads per iteration for MLP.
// ---------------------------------------------------------------------------
__global__ void __launch_bounds__(128) k_stats(const float* __restrict__ rgb,
                                               const float* __restrict__ ir) {
    int c0 = blockIdx.x * 8, b = blockIdx.y, s = blockIdx.z;
    int tid = threadIdx.x;

    const float4* x4  = (const float4*)((s == 0 ? rgb : ir) + ((size_t)b * NC + c0) * NHW);
    const float4* sa4 = (const float4*)(g_sa + (size_t)b * NHW);

    float d[8], n[8];
    #pragma unroll
    for (int k = 0; k < 8; k++) { d[k] = 0.f; n[k] = 0.f; }

    for (int g = tid; g < NG4; g += 128) {
        float4 a = sa4[g];
        #pragma unroll
        for (int k = 0; k < 8; k++) {
            float4 v = __ldcs(x4 + k * NG4 + g);
            d[k] += v.x * a.x + v.y * a.y + v.z * a.z + v.w * a.w;
            n[k] += v.x * v.x + v.y * v.y + v.z * v.z + v.w * v.w;
        }
    }
    #pragma unroll
    for (int o = 16; o > 0; o >>= 1) {
        #pragma unroll
        for (int k = 0; k < 8; k++) {
            d[k] += __shfl_down_sync(0xffffffffu, d[k], o);
            n[k] += __shfl_down_sync(0xffffffffu, n[k], o);
        }
    }
    __shared__ float sd[4][8], sn[4][8];   // [warp][channel]
    if ((tid & 31) == 0) {
        int w = tid >> 5;
        #pragma unroll
        for (int k = 0; k < 8; k++) { sd[w][k] = d[k]; sn[w][k] = n[k]; }
    }
    __syncthreads();
    if (tid < 8) {
        float dd = (sd[0][tid] + sd[1][tid]) + (sd[2][tid] + sd[3][tid]);
        float nn = (sn[0][tid] + sn[1][tid]) + (sn[2][tid] + sn[3][tid]);
        g_dot[s][b * NC + c0 + tid] = dd;
        g_nsq[s][b * NC + c0 + tid] = nn;
    }
}

// ---------------------------------------------------------------------------
// Pass 3: ordering key = dot / nx (common positive factor ||sa|| dropped:
// identical argsort order and sign). Positive count -> atomicMax(g_n[s]);
// stable rank argsort via broadcast LDS.128 loop.
// ---------------------------------------------------------------------------
__global__ void __launch_bounds__(256) k_sort() {
    int b = blockIdx.x, s = blockIdx.y;
    int tid = threadIdx.x;  // 256 == NC

    __shared__ __align__(16) float s_key[NC];

    float nx  = fmaxf(sqrtf(g_nsq[s][b * NC + tid]), EPSF);
    float sim = g_dot[s][b * NC + tid] / nx;
    s_key[tid] = sim;

    int cnt = __syncthreads_count(sim > 0.f);   // barrier also publishes s_key
    if (tid == 0) atomicMax(&g_n[s], cnt);      // batch max (reset in k_sa1)

    // stable rank: # keys strictly less, plus equal keys with smaller index
    const float4* k4 = (const float4*)s_key;
    int rank = 0;
    #pragma unroll 8
    for (int j4 = 0; j4 < NC / 4; j4++) {
        float4 k = k4[j4];                       // broadcast LDS.128
        int j = j4 * 4;
        rank += (k.x < sim) || (k.x == sim && j     < tid);
        rank += (k.y < sim) || (k.y == sim && j + 1 < tid);
        rank += (k.z < sim) || (k.z == sim && j + 2 < tid);
        rank += (k.w < sim) || (k.w == sim && j + 3 < tid);
    }
    g_ord[s][b * NC + rank] = tid;               // channel tid sits at position rank
}

// ---------------------------------------------------------------------------
// Pass 4: out = (src>=0 ? x[src] : max(rgb[lo0], ir[lo1])) * sa_sig.
// 4 channels per thread (same b,g): one sa load + one metadata set feeds
// 8 gathers/8 stores. srcmap derived inline from g_ord + g_n. Warp-uniform
// channel indices keep every gather coalesced.
// ---------------------------------------------------------------------------
__device__ __forceinline__ int src_of(const int* __restrict__ ord, int c,
                                      int n_self, int n_other) {
    if (n_other > n_self && n_self < NC) {
        if (c < n_self)  return __ldg(ord + c);
        if (c == n_self) return -1;              // extra_fea slot
        return __ldg(ord + c - 1);
    }
    return __ldg(ord + c);
}

__global__ void __launch_bounds__(256) k_out(const float* __restrict__ rgb,
                                             const float* __restrict__ ir,
                                             float* __restrict__ out) {
    int idx = blockIdx.x * blockDim.x + threadIdx.x;     // [0, NB*64*NG4)
    int g  = idx % NG4;
    int t  = idx / NG4;
    int cp = t & 63;
    int b  = t >> 6;
    int c0 = cp * 4;

    float4 a = __ldg((const float4*)(g_sa + (size_t)b * NHW) + g);

    const float4* rb = (const float4*)(rgb + (size_t)b * NC * NHW);
    const float4* ib = (const float4*)(ir  + (size_t)b * NC * NHW);

    int n0 = __ldg(&g_n[0]);
    int n1 = __ldg(&g_n[1]);
    const int* ord0 = g_ord[0] + b * NC;
    const int* ord1 = g_ord[1] + b * NC;

    int sr[4], si[4];
    #pragma unroll
    for (int k = 0; k < 4; k++) {
        sr[k] = src_of(ord0, c0 + k, n0, n1);
        si[k] = src_of(ord1, c0 + k, n1, n0);
    }

    float4 ex;  // extra_fea = max(lowest-sim rgb, lowest-sim ir); lazy
    bool need_ex = false;
    #pragma unroll
    for (int k = 0; k < 4; k++) need_ex |= (sr[k] < 0) | (si[k] < 0);
    if (need_ex) {
        float4 p = __ldcs(rb + (size_t)__ldg(ord0) * NG4 + g);
        float4 q = __ldcs(ib + (size_t)__ldg(ord1) * NG4 + g);
        ex = make_float4(fmaxf(p.x, q.x), fmaxf(p.y, q.y), fmaxf(p.z, q.z), fmaxf(p.w, q.w));
    }

    float4 vr[4], vi[4];
    #pragma unroll
    for (int k = 0; k < 4; k++)
        vr[k] = (sr[k] >= 0) ? __ldcs(rb + (size_t)sr[k] * NG4 + g) : ex;
    #pragma unroll
    for (int k = 0; k < 4; k++)
        vi[k] = (si[k] >= 0) ? __ldcs(ib + (size_t)si[k] * NG4 + g) : ex;

    size_t base_r = ((size_t)b * NC + c0) * NG4 + g;
    size_t base_i = (size_t)NB * NC * NG4 + base_r;

    #pragma unroll
    for (int k = 0; k < 4; k++)
        __stcs((float4*)out + base_r + (size_t)k * NG4,
               make_float4(vr[k].x * a.x, vr[k].y * a.y, vr[k].z * a.z, vr[k].w * a.w));
    #pragma unroll
    for (int k = 0; k < 4; k++)
        __stcs((float4*)out + base_i + (size_t)k * NG4,
               make_float4(vi[k].x * a.x, vi[k].y * a.y, vi[k].z * a.z, vi[k].w * a.w));
}

extern "C" void kernel_launch(void* const* d_in, const int* in_sizes, int n_in,
                              void* d_out, int out_size) {
    (void)in_sizes; (void)n_in; (void)out_size;
    const float* rgb = (const float*)d_in[0];
    const float* ir  = (const float*)d_in[1];
    float* out = (float*)d_out;

    k_sa1<<<dim3(7, NB, NZ), 128>>>(rgb, ir);
    k_sa2<<<dim3(7, NB), 128>>>();
    k_stats<<<dim3(NC / 8, NB, 2), 128>>>(rgb, ir);
    k_sort<<<dim3(NB, 2), 256>>>();
    k_out<<<(NB * 64 * NG4) / 256, 256>>>(rgb, ir, out);
}